// round 11
// baseline (speedup 1.0000x reference)
#include <cuda_runtime.h>
#include <cuda_fp16.h>
#include <cub/cub.cuh>
#include <stdint.h>

// ---------------- problem constants ----------------
#define HF 96
#define WF 96
#define NPOS (HF*WF)            // 9216
#define CIN 1024
#define COUT 512
#define NA 15
#define NANCH (NPOS*NA)         // 138240
#define PRE 6000
#define POST 300
#define NW 94                   // ceil(6000/64)
#define FEAT_ELEMS (1*1024*96*96)

#define RES_SCALE 2048.0f       // 2^11: residual planes scaled into fp16 normal range
#define RES_INV   (1.0f/2048.0f)

// ---------------- device scratch (static, no allocs) ----------------
__device__ __half g_featH[(size_t)NPOS*CIN];
__device__ __half g_featM[(size_t)NPOS*CIN];   // (A - Ah) * 2^11
__device__ __half g_wH[(size_t)9*CIN*COUT];    // [tap][ic][oc]
__device__ __half g_wM[(size_t)9*CIN*COUT];    // (w - wH) * 2^11
__device__ float g_Xt[(size_t)NPOS*COUT];      // conv1+BN+ReLU, [pos][oc]
__device__ float g_wpad[COUT*96];
__device__ float g_dots[(size_t)NPOS*96];
__device__ float g_box[(size_t)NANCH*4];
__device__ unsigned long long g_keys[NANCH];
__device__ unsigned long long g_keys_sorted[NANCH];
__device__ float g_bs[PRE*4];
__device__ float g_area[PRE];
__device__ int   g_valid[PRE];
__device__ unsigned long long g_mask[(size_t)PRE*NW];
__device__ unsigned char g_cub_temp[16u*1024u*1024u];

__constant__ float c_anchors[NA][4] = {
  {-15.f,  -4.f,  30.f,  19.f}, { -38.f, -16.f,  53.f,  31.f}, { -84.f, -40.f,  99.f,  55.f},
  {-176.f, -88.f, 191.f, 103.f}, {-360.f,-184.f, 375.f, 199.f},
  { -8.f,  -8.f,  23.f,  23.f}, { -24.f, -24.f,  39.f,  39.f}, { -56.f, -56.f,  71.f,  71.f},
  {-120.f,-120.f, 135.f, 135.f}, {-248.f,-248.f, 263.f, 263.f},
  { -3.f, -14.f,  18.f,  29.f}, { -14.f, -36.f,  29.f,  51.f}, { -36.f, -80.f,  51.f,  95.f},
  { -80.f,-168.f,  95.f, 183.f}, {-168.f,-344.f, 183.f, 359.f}
};

// ================= generic PTX helpers =================
__device__ __forceinline__ uint32_t smem_to_u32(const void* p) {
    uint32_t a;
    asm("{ .reg .u64 t; cvta.to.shared.u64 t, %1; cvt.u32.u64 %0, t; }" : "=r"(a) : "l"(p));
    return a;
}
__device__ __forceinline__ void cp16(uint32_t dst, const void* src, bool valid) {
    int sz = valid ? 16 : 0;
    asm volatile("cp.async.cg.shared.global [%0], [%1], 16, %2;"
                 :: "r"(dst), "l"(src), "r"(sz) : "memory");
}
#define CP_COMMIT()  asm volatile("cp.async.commit_group;" ::: "memory")
#define CP_WAIT2()   asm volatile("cp.async.wait_group 2;" ::: "memory")
#define CP_WAIT0()   asm volatile("cp.async.wait_group 0;" ::: "memory")

__device__ __forceinline__ void ldsm_x4(uint32_t addr, uint32_t* r) {
    asm volatile("ldmatrix.sync.aligned.m8n8.x4.shared.b16 {%0,%1,%2,%3}, [%4];"
                 : "=r"(r[0]), "=r"(r[1]), "=r"(r[2]), "=r"(r[3]) : "r"(addr));
}
__device__ __forceinline__ void ldsm_x4_t(uint32_t addr, uint32_t* r) {
    asm volatile("ldmatrix.sync.aligned.m8n8.x4.trans.shared.b16 {%0,%1,%2,%3}, [%4];"
                 : "=r"(r[0]), "=r"(r[1]), "=r"(r[2]), "=r"(r[3]) : "r"(addr));
}
// fp16 MMA, in-TC accumulate (used only for scaled correction terms)
__device__ __forceinline__ void mma_f16(float* d, const uint32_t* a, uint32_t b0, uint32_t b1) {
    asm volatile("mma.sync.aligned.m16n8k16.row.col.f32.f16.f16.f32 "
                 "{%0,%1,%2,%3},{%4,%5,%6,%7},{%8,%9},{%0,%1,%2,%3};"
                 : "+f"(d[0]), "+f"(d[1]), "+f"(d[2]), "+f"(d[3])
                 : "r"(a[0]), "r"(a[1]), "r"(a[2]), "r"(a[3]), "r"(b0), "r"(b1));
}
// zero-C fp16 MMA: D = A*B (large accumulator kept OUT of the TC truncating datapath)
__device__ __forceinline__ void mma_f16_zc(float* d, const uint32_t* a, uint32_t b0, uint32_t b1) {
    asm volatile("mma.sync.aligned.m16n8k16.row.col.f32.f16.f16.f32 "
                 "{%0,%1,%2,%3},{%4,%5,%6,%7},{%8,%9},{%10,%11,%12,%13};"
                 : "=f"(d[0]), "=f"(d[1]), "=f"(d[2]), "=f"(d[3])
                 : "r"(a[0]), "r"(a[1]), "r"(a[2]), "r"(a[3]), "r"(b0), "r"(b1),
                   "f"(0.f), "f"(0.f), "f"(0.f), "f"(0.f));
}

// ---------------- prep: split features fp32 -> 2 fp16 planes (scaled residual) ----------------
__global__ void split_feat_kernel(const float* __restrict__ in) {
    __shared__ float tile[32][33];
    int px = blockIdx.x*32 + threadIdx.x;
    int ic = blockIdx.y*32 + threadIdx.y;
    tile[threadIdx.y][threadIdx.x] = in[(size_t)ic*NPOS + px];
    __syncthreads();
    int opos = blockIdx.x*32 + threadIdx.y;
    int oic  = blockIdx.y*32 + threadIdx.x;
    float v = tile[threadIdx.x][threadIdx.y];
    __half h = __float2half(v);
    __half m = __float2half((v - __half2float(h)) * RES_SCALE);
    size_t o = (size_t)opos*CIN + oic;
    g_featH[o] = h; g_featM[o] = m;
}

// ---------------- prep: split conv weights -> [tap][ic][oc], scaled residual ----------------
__global__ void split_w_kernel(const float* __restrict__ w) {
    size_t t = (size_t)blockIdx.x*256 + threadIdx.x;
    if (t >= (size_t)9*CIN*COUT) return;
    int tap = (int)(t / (CIN*COUT));
    int rem = (int)(t % (CIN*COUT));
    int ic = rem / COUT, oc = rem % COUT;
    float v = w[((size_t)oc*CIN + ic)*9 + tap];
    __half h = __float2half(v);
    __half m = __float2half((v - __half2float(h)) * RES_SCALE);
    size_t o = ((size_t)tap*CIN + ic)*COUT + oc;
    g_wH[o] = h; g_wM[o] = m;
}

// ---------------- prep: pack head weights ----------------
__global__ void prep_wpad_kernel(const float* __restrict__ score_w,
                                 const float* __restrict__ bbox_w) {
    int t = blockIdx.x*256 + threadIdx.x;
    if (t >= COUT*96) return;
    int c = t / 96, o = t % 96;
    float v = 0.f;
    if (o < 30)       v = score_w[(size_t)o*512 + c];
    else if (o < 90)  v = bbox_w[(size_t)(o-30)*512 + c];
    g_wpad[t] = v;
}

// ================= conv1 via mma.sync fp16 2-plane (scaled residuals) ====
// 2 CTAs/SM: CTA tile 128M x 64N, 256 threads = 4(m) x 2(n) warps, warp tile 32x32.
// K: 9 taps x 32 ic-chunks = 288 iters, 3-stage cp.async pipeline (loads AFTER compute).
// hh: zero-C MMA per k16 step, drained to fp32 regs via FADD (sequential-k order).
// Corrections hm+mh (x 2^11) accumulate in-TC; epilogue adds clo * 2^-11.
// smem per stage: A 2pl x 8KB + B 2pl x 4KB = 24KB; 3 stages = 72KB -> 2 CTAs/SM.
#define STAGE   24576
#define B_OFF   16384
#define CONV_SMEM (3*STAGE + 1024)

__device__ __forceinline__ void conv_issue_load(int iter, uint32_t sbase, int mbase,
                                                int ntile, int tid) {
    const int tap = iter >> 5;
    const int chunk = iter & 31;
    const int ky = tap/3 - 1, kx = tap%3 - 1;
    const uint32_t stg = sbase + (uint32_t)(iter % 3)*STAGE;
    // ---- A: 128 rows x 4 uint4 x 2 planes; 256 threads -> 2 u per thread ----
    {
        int row = tid >> 1, u0 = (tid & 1)*2;
        int p = mbase + row;
        int yy = p/96 + ky, xx = p%96 + kx;
        bool valid = ((unsigned)yy < 96u) && ((unsigned)xx < 96u);
        size_t base = 0;
        if (valid) base = ((size_t)(p + ky*96 + kx)*128 + chunk*4) * 16;  // bytes
        #pragma unroll
        for (int du = 0; du < 2; du++) {
            int u = u0 + du;
            uint32_t su = (uint32_t)(u ^ ((row >> 1) & 3));
            uint32_t dst = stg + (uint32_t)row*64 + su*16;
            size_t idx = base + (size_t)u*16;
            cp16(dst,        (const char*)g_featH + idx, valid);
            cp16(dst + 8192, (const char*)g_featM + idx, valid);
        }
    }
    // ---- B: 32 k-rows x 8 uint4 (64 oc) x 2 planes; 1 per thread ----
    {
        int row = tid >> 3, u = tid & 7;
        uint32_t su = (uint32_t)(u ^ (row & 7));
        uint32_t dst = stg + B_OFF + (uint32_t)row*128 + su*16;
        size_t off = (((size_t)tap*CIN + chunk*32 + row)*COUT + (size_t)ntile*64 + u*8) * 2;
        cp16(dst,        (const char*)g_wH + off, true);
        cp16(dst + 4096, (const char*)g_wM + off, true);
    }
    CP_COMMIT();
}

__global__ void __launch_bounds__(256, 2) conv_mma_kernel(
    const float* __restrict__ conv_b, const float* __restrict__ gamma,
    const float* __restrict__ beta, const float* __restrict__ mean,
    const float* __restrict__ var) {
    extern __shared__ char smem_raw[];
    uint32_t sb0 = smem_to_u32(smem_raw);
    uint32_t sbase = (sb0 + 1023u) & ~1023u;

    __shared__ float s_sc[64];
    __shared__ float s_sh[64];

    const int tid = threadIdx.x;
    const int lane = tid & 31;
    const int wid = tid >> 5;
    const int wm = wid & 3;        // warp m (0..3) -> 32 rows each
    const int wn = wid >> 2;       // warp n (0..1) -> 32 oc each
    const int mbase = blockIdx.x * 128;
    const int ntile = blockIdx.y;  // 0..7, 64 oc each

    if (tid < 64) {
        int oc = ntile*64 + tid;
        float sc = gamma[oc] / sqrtf(var[oc] + 1e-5f);
        s_sc[tid] = sc;
        s_sh[tid] = (conv_b[oc] - mean[oc]) * sc + beta[oc];
    }

    float chi[2][4][4], clo[2][4][4];
    #pragma unroll
    for (int t = 0; t < 2; t++)
        #pragma unroll
        for (int j = 0; j < 4; j++)
            #pragma unroll
            for (int q = 0; q < 4; q++) { chi[t][j][q] = 0.f; clo[t][j][q] = 0.f; }

    conv_issue_load(0, sbase, mbase, ntile, tid);
    conv_issue_load(1, sbase, mbase, ntile, tid);
    conv_issue_load(2, sbase, mbase, ntile, tid);

    const int a_row_lo = ((lane >> 3) & 1)*8 + (lane & 7);
    const int a_uhalf = lane >> 4;
    const int b_r_lo = ((lane >> 3) & 1)*8 + (lane & 7);
    const int b_uhalf = lane >> 4;

    for (int iter = 0; iter < 288; iter++) {
        if (iter >= 285) { CP_WAIT0(); } else { CP_WAIT2(); }
        __syncthreads();

        const uint32_t abase = sbase + (uint32_t)(iter % 3)*STAGE;
        const uint32_t bbase = abase + B_OFF;

        #pragma unroll
        for (int s = 0; s < 2; s++) {
            uint32_t Af[2][2][4];
            uint32_t Bf[2][2][4];
            #pragma unroll
            for (int pl = 0; pl < 2; pl++) {
                #pragma unroll
                for (int t = 0; t < 2; t++) {
                    int row = wm*32 + t*16 + a_row_lo;
                    int u = s*2 + a_uhalf;
                    int su = u ^ ((row >> 1) & 3);
                    ldsm_x4(abase + (uint32_t)pl*8192 + (uint32_t)row*64 + (uint32_t)su*16, Af[pl][t]);
                }
                #pragma unroll
                for (int b = 0; b < 2; b++) {
                    int r = s*16 + b_r_lo;
                    int u = wn*4 + b*2 + b_uhalf;
                    int su = u ^ (r & 7);
                    ldsm_x4_t(bbase + (uint32_t)pl*4096 + (uint32_t)r*128 + (uint32_t)su*16, Bf[pl][b]);
                }
            }
            #pragma unroll
            for (int t = 0; t < 2; t++) {
                #pragma unroll
                for (int b = 0; b < 2; b++) {
                    #pragma unroll
                    for (int h = 0; h < 2; h++) {
                        int j = b*2 + h;
                        uint32_t b0h = Bf[0][b][h*2], b1h = Bf[0][b][h*2+1];
                        uint32_t b0m = Bf[1][b][h*2], b1m = Bf[1][b][h*2+1];
                        // hh: fresh product, drained via fp32 FADD (sequential k order)
                        float dtmp[4];
                        mma_f16_zc(dtmp, Af[0][t], b0h, b1h);
                        chi[t][j][0] += dtmp[0];
                        chi[t][j][1] += dtmp[1];
                        chi[t][j][2] += dtmp[2];
                        chi[t][j][3] += dtmp[3];
                        // corrections (x 2^11): in-TC accumulate
                        mma_f16(clo[t][j], Af[0][t], b0m, b1m);  // Ah * wM'
                        mma_f16(clo[t][j], Af[1][t], b0h, b1h);  // Am' * wH
                    }
                }
            }
        }
        __syncthreads();
        if (iter + 3 < 288) conv_issue_load(iter + 3, sbase, mbase, ntile, tid);
    }

    // epilogue: BN + ReLU, direct stores to g_Xt[pos][oc]
    __syncthreads();
    #pragma unroll
    for (int t = 0; t < 2; t++) {
        #pragma unroll
        for (int j = 0; j < 4; j++) {
            int oc_l = wn*32 + j*8 + (lane & 3)*2;
            float sc0 = s_sc[oc_l],   sh0 = s_sh[oc_l];
            float sc1 = s_sc[oc_l+1], sh1 = s_sh[oc_l+1];
            int r0 = mbase + wm*32 + t*16 + (lane >> 2);
            int r1 = r0 + 8;
            float a0 = chi[t][j][0] + clo[t][j][0]*RES_INV;
            float a1 = chi[t][j][1] + clo[t][j][1]*RES_INV;
            float a2 = chi[t][j][2] + clo[t][j][2]*RES_INV;
            float a3 = chi[t][j][3] + clo[t][j][3]*RES_INV;
            float2 v0, v1;
            v0.x = fmaxf(a0*sc0 + sh0, 0.f);
            v0.y = fmaxf(a1*sc1 + sh1, 0.f);
            v1.x = fmaxf(a2*sc0 + sh0, 0.f);
            v1.y = fmaxf(a3*sc1 + sh1, 0.f);
            *(float2*)&g_Xt[(size_t)r0*512 + ntile*64 + oc_l] = v0;
            *(float2*)&g_Xt[(size_t)r1*512 + ntile*64 + oc_l] = v1;
        }
    }
}

// ---------------- heads 1x1 GEMM ----------------
__global__ void __launch_bounds__(256) heads_kernel(
    const float* __restrict__ score_b, const float* __restrict__ bbox_b) {
    __shared__ float sv[32][33];
    __shared__ float sw[32][96];
    const int pos0 = blockIdx.x * 32;
    const int tid = threadIdx.x;
    const int og = tid & 31, pg = tid >> 5;

    float acc[3][4];
    #pragma unroll
    for (int m=0;m<3;m++)
        #pragma unroll
        for (int q=0;q<4;q++) acc[m][q]=0.f;

    for (int c0=0; c0<512; c0+=32) {
        {
            int pos_l = tid >> 5, c_l = tid & 31;
            #pragma unroll
            for (int r=0;r<4;r++)
                sv[c_l][pos_l + r*8] = g_Xt[(size_t)(pos0 + pos_l + r*8)*512 + c0 + c_l];
        }
        #pragma unroll
        for (int r=0;r<12;r++) {
            int e = r*256 + tid;
            int ccc = e/96, oo = e%96;
            sw[ccc][oo] = g_wpad[(size_t)(c0+ccc)*96 + oo];
        }
        __syncthreads();
        #pragma unroll
        for (int c=0;c<32;c++) {
            float w0 = sw[c][og], w1 = sw[c][og+32], w2 = sw[c][og+64];
            #pragma unroll
            for (int q=0;q<4;q++) {
                float v = sv[c][pg*4 + q];
                acc[0][q] += w0*v; acc[1][q] += w1*v; acc[2][q] += w2*v;
            }
        }
        __syncthreads();
    }
    #pragma unroll
    for (int m=0;m<3;m++) {
        int o = og + m*32;
        if (o >= 90) continue;
        float b = (o < 30) ? score_b[o] : bbox_b[o-30];
        #pragma unroll
        for (int q=0;q<4;q++)
            g_dots[(size_t)(pos0 + pg*4 + q)*96 + o] = acc[m][q] + b;
    }
}

// ---------------- per-anchor proposal prep ----------------
__global__ void proposal_kernel(const float* __restrict__ im_info) {
    int i = blockIdx.x*256 + threadIdx.x;
    if (i >= NANCH) return;
    int pos = i / NA, a = i % NA;
    int hy = pos / 96, wx = pos % 96;
    const float* dt = &g_dots[(size_t)pos*96];

    float bg = dt[a], fg = dt[15+a];
    float mx = fmaxf(bg, fg);
    float eb = expf(bg - mx), ef = expf(fg - mx);
    float score = ef / (eb + ef);

    float d0 = dt[30+4*a+0], d1 = dt[30+4*a+1], d2 = dt[30+4*a+2], d3 = dt[30+4*a+3];

    float ax1 = c_anchors[a][0] + wx*16.f;
    float ay1 = c_anchors[a][1] + hy*16.f;
    float ax2 = c_anchors[a][2] + wx*16.f;
    float ay2 = c_anchors[a][3] + hy*16.f;
    float aw = ax2 - ax1 + 1.f, ah = ay2 - ay1 + 1.f;
    float acx = ax1 + 0.5f*aw, acy = ay1 + 0.5f*ah;
    float px = d0*aw + acx, py = d1*ah + acy;
    float pw = expf(d2)*aw, ph = expf(d3)*ah;

    float imh = im_info[0], imw = im_info[1], ims = im_info[2];
    float x1 = fminf(fmaxf(px - 0.5f*pw, 0.f), imw - 1.f);
    float y1 = fminf(fmaxf(py - 0.5f*ph, 0.f), imh - 1.f);
    float x2 = fminf(fmaxf(px + 0.5f*pw - 1.f, 0.f), imw - 1.f);
    float y2 = fminf(fmaxf(py + 0.5f*ph - 1.f, 0.f), imh - 1.f);

    float ms = 16.f * ims;
    bool keep = ((x2 - x1 + 1.f) >= ms) && ((y2 - y1 + 1.f) >= ms);
    float s = keep ? score : -1.f;

    g_box[(size_t)i*4+0] = x1;
    g_box[(size_t)i*4+1] = y1;
    g_box[(size_t)i*4+2] = x2;
    g_box[(size_t)i*4+3] = y2;

    unsigned int b = __float_as_uint(s);
    unsigned int u = (b & 0x80000000u) ? ~b : (b | 0x80000000u);
    // low 32 bits = plain index; sort only bits [32,64) — stable LSD keeps
    // index-ascending order for score ties (reference top_k semantics)
    g_keys[i] = ((unsigned long long)u << 32) | (unsigned int)i;
}

__global__ void gather_kernel() {
    int j = blockIdx.x*256 + threadIdx.x;
    if (j >= PRE) return;
    unsigned long long k = g_keys_sorted[j];
    unsigned int idx = (unsigned int)(k & 0xFFFFFFFFull);
    int valid = (int)(k >> 63);
    float x1 = g_box[(size_t)idx*4+0], y1 = g_box[(size_t)idx*4+1];
    float x2 = g_box[(size_t)idx*4+2], y2 = g_box[(size_t)idx*4+3];
    g_bs[j*4+0]=x1; g_bs[j*4+1]=y1; g_bs[j*4+2]=x2; g_bs[j*4+3]=y2;
    g_area[j] = (x2 - x1 + 1.f) * (y2 - y1 + 1.f);
    g_valid[j] = valid;
}

__global__ void nms_mask_kernel() {
    // scan only ORs words >= word(i), so lower-triangle blocks are never read
    if (blockIdx.x < blockIdx.y) return;
    __shared__ float jb[64][4];
    __shared__ float ja[64];
    const int jw = blockIdx.x;
    const int t  = threadIdx.x;
    const int j0 = jw*64;
    if (j0 + t < PRE) {
        jb[t][0]=g_bs[(j0+t)*4+0]; jb[t][1]=g_bs[(j0+t)*4+1];
        jb[t][2]=g_bs[(j0+t)*4+2]; jb[t][3]=g_bs[(j0+t)*4+3];
        ja[t]=g_area[j0+t];
    }
    __syncthreads();
    const int i = blockIdx.y*64 + t;
    if (i >= PRE) return;
    float x1=g_bs[i*4+0], y1=g_bs[i*4+1], x2=g_bs[i*4+2], y2=g_bs[i*4+3];
    float ar=g_area[i];
    unsigned long long bits = 0ull;
    int lim = min(64, PRE - j0);
    for (int jj=0; jj<lim; jj++) {
        float xx1 = fmaxf(x1, jb[jj][0]);
        float yy1 = fmaxf(y1, jb[jj][1]);
        float xx2 = fminf(x2, jb[jj][2]);
        float yy2 = fminf(y2, jb[jj][3]);
        float iw = fmaxf(0.f, xx2 - xx1 + 1.f);
        float ih = fmaxf(0.f, yy2 - yy1 + 1.f);
        float inter = iw*ih;
        float iou = inter / (ar + ja[jj] - inter);
        if (iou > 0.7f) bits |= (1ull << jj);
    }
    g_mask[(size_t)i*NW + jw] = bits;
}

__global__ void nms_scan_kernel(float* __restrict__ rois) {
    __shared__ unsigned long long removed[NW];
    __shared__ int s_keep[POST];
    __shared__ int s_j;
    const int tid = threadIdx.x;
    for (int w = tid; w < NW; w += blockDim.x) {
        unsigned long long r = 0ull;
        for (int b = 0; b < 64; b++) {
            int j = w*64 + b;
            if (j >= PRE || !g_valid[j]) r |= (1ull << b);
        }
        removed[w] = r;
    }
    __syncthreads();

    int count = 0;
    for (int w = 0; w < NW; w++) {
        while (count < POST) {
            if (tid == 0) {
                unsigned long long live = ~removed[w];
                s_j = live ? (w*64 + __ffsll((long long)live) - 1) : -1;
            }
            __syncthreads();
            int j = s_j;
            __syncthreads();
            if (j < 0) break;
            if (tid == 0) s_keep[count] = j;
            count++;
            // scan only moves forward: words < w never revisited
            for (int ww = w + tid; ww < NW; ww += blockDim.x)
                removed[ww] |= g_mask[(size_t)j*NW + ww];
            __syncthreads();
        }
        if (count >= POST) break;
    }
    __syncthreads();

    for (int r = tid; r < POST; r += blockDim.x) {
        float b0=0.f,b1=0.f,b2=0.f,b3=0.f;
        if (r < count) {
            int j = s_keep[r];
            b0 = g_bs[j*4+0]; b1 = g_bs[j*4+1]; b2 = g_bs[j*4+2]; b3 = g_bs[j*4+3];
        }
        rois[r*5+0] = 0.f;
        rois[r*5+1] = b0; rois[r*5+2] = b1; rois[r*5+3] = b2; rois[r*5+4] = b3;
    }
}

// ---------------- launch ----------------
extern "C" void kernel_launch(void* const* d_in, const int* in_sizes, int n_in,
                              void* d_out, int out_size) {
    const float* features = (const float*)d_in[0];
    const float* im_info  = (const float*)d_in[1];
    const float* conv1_w  = (const float*)d_in[2];
    const float* conv1_b  = (const float*)d_in[3];
    const float* bn_gamma = (const float*)d_in[4];
    const float* bn_beta  = (const float*)d_in[5];
    const float* bn_mean  = (const float*)d_in[6];
    const float* bn_var   = (const float*)d_in[7];
    const float* score_w  = (const float*)d_in[8];
    const float* score_b  = (const float*)d_in[9];
    const float* bbox_w   = (const float*)d_in[10];
    const float* bbox_b   = (const float*)d_in[11];

    float* out = (float*)d_out;

    // 1) features passthrough
    cudaMemcpyAsync(out, features, (size_t)FEAT_ELEMS*sizeof(float),
                    cudaMemcpyDeviceToDevice, 0);

    // 2) prep: fp16 2-plane splits (scaled residual) + head weight pack
    split_feat_kernel<<<dim3(NPOS/32, CIN/32), dim3(32,32)>>>(features);
    split_w_kernel<<<(int)(((size_t)9*CIN*COUT + 255)/256), 256>>>(conv1_w);
    prep_wpad_kernel<<<(COUT*96 + 255)/256, 256>>>(score_w, bbox_w);

    // 3) conv1 + BN + ReLU via mma.sync fp16 2-plane, 2 CTAs/SM
    cudaFuncSetAttribute(conv_mma_kernel,
                         cudaFuncAttributeMaxDynamicSharedMemorySize, CONV_SMEM);
    conv_mma_kernel<<<dim3(72, 8), 256, CONV_SMEM>>>(
        conv1_b, bn_gamma, bn_beta, bn_mean, bn_var);

    // 4) heads
    heads_kernel<<<NPOS/32, 256>>>(score_b, bbox_b);

    // 5) per-anchor proposal prep
    proposal_kernel<<<(NANCH + 255)/256, 256>>>(im_info);

    // 6) sort keys descending on bits [32,64) only (stable -> index-asc ties)
    {
        void *keys_p = nullptr, *keys_sorted_p = nullptr, *temp_p = nullptr;
        cudaGetSymbolAddress(&keys_p, g_keys);
        cudaGetSymbolAddress(&keys_sorted_p, g_keys_sorted);
        cudaGetSymbolAddress(&temp_p, g_cub_temp);
        size_t tb = 0;
        cub::DeviceRadixSort::SortKeysDescending(
            nullptr, tb,
            (const unsigned long long*)keys_p, (unsigned long long*)keys_sorted_p,
            NANCH, 32, 64, (cudaStream_t)0);
        if (tb > sizeof(g_cub_temp)) tb = sizeof(g_cub_temp);
        cub::DeviceRadixSort::SortKeysDescending(
            temp_p, tb,
            (const unsigned long long*)keys_p, (unsigned long long*)keys_sorted_p,
            NANCH, 32, 64, (cudaStream_t)0);
    }

    // 7) gather top-6000
    gather_kernel<<<(PRE + 255)/256, 256>>>();

    // 8) NMS mask (upper triangle only)
    nms_mask_kernel<<<dim3(NW, NW), 64>>>();

    // 9) NMS scan + write rois
    nms_scan_kernel<<<1, 128>>>(out + FEAT_ELEMS);

    (void)in_sizes; (void)n_in; (void)out_size;
}

// round 12
// speedup vs baseline: 1.0497x; 1.0497x over previous
#include <cuda_runtime.h>
#include <cuda_fp16.h>
#include <cub/cub.cuh>
#include <stdint.h>

// ---------------- problem constants ----------------
#define HF 96
#define WF 96
#define NPOS (HF*WF)            // 9216
#define CIN 1024
#define COUT 512
#define NA 15
#define NANCH (NPOS*NA)         // 138240
#define PRE 6000
#define POST 300
#define NW 94                   // ceil(6000/64)
#define FEAT_ELEMS (1*1024*96*96)

#define RES_SCALE 2048.0f       // 2^11: residual planes scaled into fp16 normal range
#define RES_INV   (1.0f/2048.0f)

// ---------------- device scratch (static, no allocs) ----------------
__device__ __half g_featH[(size_t)NPOS*CIN];
__device__ __half g_featM[(size_t)NPOS*CIN];   // (A - Ah) * 2^11
__device__ __half g_wH[(size_t)9*CIN*COUT];    // [tap][ic][oc]
__device__ __half g_wM[(size_t)9*CIN*COUT];    // (w - wH) * 2^11
__device__ float g_Xt[(size_t)NPOS*COUT];      // conv1+BN+ReLU, [pos][oc]
__device__ float g_wpad[COUT*96];
__device__ float g_dots[(size_t)NPOS*96];
__device__ float g_box[(size_t)NANCH*4];
__device__ unsigned long long g_keys[NANCH];
__device__ unsigned long long g_keys_sorted[NANCH];
__device__ float g_bs[PRE*4];
__device__ float g_area[PRE];
__device__ int   g_valid[PRE];
__device__ unsigned long long g_mask[(size_t)PRE*NW];
__device__ unsigned char g_cub_temp[16u*1024u*1024u];

__constant__ float c_anchors[NA][4] = {
  {-15.f,  -4.f,  30.f,  19.f}, { -38.f, -16.f,  53.f,  31.f}, { -84.f, -40.f,  99.f,  55.f},
  {-176.f, -88.f, 191.f, 103.f}, {-360.f,-184.f, 375.f, 199.f},
  { -8.f,  -8.f,  23.f,  23.f}, { -24.f, -24.f,  39.f,  39.f}, { -56.f, -56.f,  71.f,  71.f},
  {-120.f,-120.f, 135.f, 135.f}, {-248.f,-248.f, 263.f, 263.f},
  { -3.f, -14.f,  18.f,  29.f}, { -14.f, -36.f,  29.f,  51.f}, { -36.f, -80.f,  51.f,  95.f},
  { -80.f,-168.f,  95.f, 183.f}, {-168.f,-344.f, 183.f, 359.f}
};

// ================= generic PTX helpers =================
__device__ __forceinline__ uint32_t smem_to_u32(const void* p) {
    uint32_t a;
    asm("{ .reg .u64 t; cvta.to.shared.u64 t, %1; cvt.u32.u64 %0, t; }" : "=r"(a) : "l"(p));
    return a;
}
__device__ __forceinline__ void cp16(uint32_t dst, const void* src, bool valid) {
    int sz = valid ? 16 : 0;
    asm volatile("cp.async.cg.shared.global [%0], [%1], 16, %2;"
                 :: "r"(dst), "l"(src), "r"(sz) : "memory");
}
#define CP_COMMIT()  asm volatile("cp.async.commit_group;" ::: "memory")
#define CP_WAIT2()   asm volatile("cp.async.wait_group 2;" ::: "memory")
#define CP_WAIT0()   asm volatile("cp.async.wait_group 0;" ::: "memory")

__device__ __forceinline__ void ldsm_x4(uint32_t addr, uint32_t* r) {
    asm volatile("ldmatrix.sync.aligned.m8n8.x4.shared.b16 {%0,%1,%2,%3}, [%4];"
                 : "=r"(r[0]), "=r"(r[1]), "=r"(r[2]), "=r"(r[3]) : "r"(addr));
}
__device__ __forceinline__ void ldsm_x4_t(uint32_t addr, uint32_t* r) {
    asm volatile("ldmatrix.sync.aligned.m8n8.x4.trans.shared.b16 {%0,%1,%2,%3}, [%4];"
                 : "=r"(r[0]), "=r"(r[1]), "=r"(r[2]), "=r"(r[3]) : "r"(addr));
}
// fp16 MMA, in-TC accumulate (used only for scaled correction terms)
__device__ __forceinline__ void mma_f16(float* d, const uint32_t* a, uint32_t b0, uint32_t b1) {
    asm volatile("mma.sync.aligned.m16n8k16.row.col.f32.f16.f16.f32 "
                 "{%0,%1,%2,%3},{%4,%5,%6,%7},{%8,%9},{%0,%1,%2,%3};"
                 : "+f"(d[0]), "+f"(d[1]), "+f"(d[2]), "+f"(d[3])
                 : "r"(a[0]), "r"(a[1]), "r"(a[2]), "r"(a[3]), "r"(b0), "r"(b1));
}
// zero-C fp16 MMA: D = A*B (large accumulator kept OUT of the TC truncating datapath)
__device__ __forceinline__ void mma_f16_zc(float* d, const uint32_t* a, uint32_t b0, uint32_t b1) {
    asm volatile("mma.sync.aligned.m16n8k16.row.col.f32.f16.f16.f32 "
                 "{%0,%1,%2,%3},{%4,%5,%6,%7},{%8,%9},{%10,%11,%12,%13};"
                 : "=f"(d[0]), "=f"(d[1]), "=f"(d[2]), "=f"(d[3])
                 : "r"(a[0]), "r"(a[1]), "r"(a[2]), "r"(a[3]), "r"(b0), "r"(b1),
                   "f"(0.f), "f"(0.f), "f"(0.f), "f"(0.f));
}

// ---------------- prep: split features fp32 -> 2 fp16 planes (scaled residual) ----------------
__global__ void split_feat_kernel(const float* __restrict__ in) {
    __shared__ float tile[32][33];
    int px = blockIdx.x*32 + threadIdx.x;
    int ic = blockIdx.y*32 + threadIdx.y;
    tile[threadIdx.y][threadIdx.x] = in[(size_t)ic*NPOS + px];
    __syncthreads();
    int opos = blockIdx.x*32 + threadIdx.y;
    int oic  = blockIdx.y*32 + threadIdx.x;
    float v = tile[threadIdx.x][threadIdx.y];
    __half h = __float2half(v);
    __half m = __float2half((v - __half2float(h)) * RES_SCALE);
    size_t o = (size_t)opos*CIN + oic;
    g_featH[o] = h; g_featM[o] = m;
}

// ---------------- prep: split conv weights -> [tap][ic][oc], scaled residual ----------------
__global__ void split_w_kernel(const float* __restrict__ w) {
    size_t t = (size_t)blockIdx.x*256 + threadIdx.x;
    if (t >= (size_t)9*CIN*COUT) return;
    int tap = (int)(t / (CIN*COUT));
    int rem = (int)(t % (CIN*COUT));
    int ic = rem / COUT, oc = rem % COUT;
    float v = w[((size_t)oc*CIN + ic)*9 + tap];
    __half h = __float2half(v);
    __half m = __float2half((v - __half2float(h)) * RES_SCALE);
    size_t o = ((size_t)tap*CIN + ic)*COUT + oc;
    g_wH[o] = h; g_wM[o] = m;
}

// ---------------- prep: pack head weights ----------------
__global__ void prep_wpad_kernel(const float* __restrict__ score_w,
                                 const float* __restrict__ bbox_w) {
    int t = blockIdx.x*256 + threadIdx.x;
    if (t >= COUT*96) return;
    int c = t / 96, o = t % 96;
    float v = 0.f;
    if (o < 30)       v = score_w[(size_t)o*512 + c];
    else if (o < 90)  v = bbox_w[(size_t)(o-30)*512 + c];
    g_wpad[t] = v;
}

// ================= conv1 via mma.sync fp16 2-plane (scaled residuals) ====
// Round-10 structure (loads AFTER compute) but 4 stages -> single barrier/iter:
// load for iter+3 targets stage (i+3)%4 == (i-1)%4, whose readers (iter i-1 compute)
// are guaranteed done once any warp passed the top-of-iter-i barrier.
// CTA tile: 128M x 128N, 512 threads = 4(m) x 4(n) warps, warp tile 32M x 32N.
// K: 9 taps x 32 ic-chunks = 288 iters.
// hh: zero-C MMA per k16 step, drained to fp32 regs via FADD (sequential-k order).
// Corrections hm+mh (x 2^11) accumulate in-TC; epilogue adds clo * 2^-11.
// smem per stage: A 2pl x 8KB + B 2pl x 8KB = 32KB; 4 stages = 128KB.
#define STAGE   32768
#define B_OFF   16384
#define CONV_SMEM (4*STAGE + 1024)

__device__ __forceinline__ void conv_issue_load(int iter, uint32_t sbase, int mbase,
                                                int ntile, int tid) {
    const int tap = iter >> 5;
    const int chunk = iter & 31;
    const int ky = tap/3 - 1, kx = tap%3 - 1;
    const uint32_t stg = sbase + (uint32_t)(iter & 3)*STAGE;
    // ---- A: 128 rows x 4 uint4 x 2 planes ----
    {
        int row = tid >> 2, u = tid & 3;
        int p = mbase + row;
        int yy = p/96 + ky, xx = p%96 + kx;
        bool valid = ((unsigned)yy < 96u) && ((unsigned)xx < 96u);
        size_t idx = 0;
        if (valid) idx = ((size_t)(p + ky*96 + kx)*128 + chunk*4 + u) * 16;  // bytes
        uint32_t su = (uint32_t)(u ^ ((row >> 1) & 3));
        uint32_t dst = stg + (uint32_t)row*64 + su*16;
        cp16(dst,        (const char*)g_featH + idx, valid);
        cp16(dst + 8192, (const char*)g_featM + idx, valid);
    }
    // ---- B: 32 k-rows x 16 uint4 (128 oc) x 2 planes ----
    {
        int row = tid >> 4, u = tid & 15;
        uint32_t su = (uint32_t)(u ^ (row & 7));
        uint32_t dst = stg + B_OFF + (uint32_t)row*256 + su*16;
        size_t off = (((size_t)tap*CIN + chunk*32 + row)*COUT + (size_t)ntile*128 + u*8) * 2;
        cp16(dst,        (const char*)g_wH + off, true);
        cp16(dst + 8192, (const char*)g_wM + off, true);
    }
    CP_COMMIT();
}

__global__ void __launch_bounds__(512, 1) conv_mma_kernel(
    const float* __restrict__ conv_b, const float* __restrict__ gamma,
    const float* __restrict__ beta, const float* __restrict__ mean,
    const float* __restrict__ var) {
    extern __shared__ char smem_raw[];
    uint32_t sb0 = smem_to_u32(smem_raw);
    uint32_t sbase = (sb0 + 1023u) & ~1023u;

    __shared__ float s_sc[128];
    __shared__ float s_sh[128];

    const int tid = threadIdx.x;
    const int lane = tid & 31;
    const int wid = tid >> 5;
    const int wm = wid & 3;        // warp m (0..3) -> 32 rows each
    const int wn = wid >> 2;       // warp n (0..3) -> 32 oc each
    const int mbase = blockIdx.x * 128;
    const int ntile = blockIdx.y;  // 0..3, 128 oc each

    if (tid < 128) {
        int oc = ntile*128 + tid;
        float sc = gamma[oc] / sqrtf(var[oc] + 1e-5f);
        s_sc[tid] = sc;
        s_sh[tid] = (conv_b[oc] - mean[oc]) * sc + beta[oc];
    }

    float chi[2][4][4], clo[2][4][4];
    #pragma unroll
    for (int t = 0; t < 2; t++)
        #pragma unroll
        for (int j = 0; j < 4; j++)
            #pragma unroll
            for (int q = 0; q < 4; q++) { chi[t][j][q] = 0.f; clo[t][j][q] = 0.f; }

    conv_issue_load(0, sbase, mbase, ntile, tid);
    conv_issue_load(1, sbase, mbase, ntile, tid);
    conv_issue_load(2, sbase, mbase, ntile, tid);

    const int a_row_lo = ((lane >> 3) & 1)*8 + (lane & 7);
    const int a_uhalf = lane >> 4;
    const int b_r_lo = ((lane >> 3) & 1)*8 + (lane & 7);
    const int b_uhalf = lane >> 4;

    for (int iter = 0; iter < 288; iter++) {
        if (iter >= 285) { CP_WAIT0(); } else { CP_WAIT2(); }
        __syncthreads();   // single barrier per iter (4 stages make trailing sync unnecessary)

        const uint32_t abase = sbase + (uint32_t)(iter & 3)*STAGE;
        const uint32_t bbase = abase + B_OFF;

        #pragma unroll
        for (int s = 0; s < 2; s++) {
            uint32_t Af[2][2][4];
            uint32_t Bf[2][2][4];
            #pragma unroll
            for (int pl = 0; pl < 2; pl++) {
                #pragma unroll
                for (int t = 0; t < 2; t++) {
                    int row = wm*32 + t*16 + a_row_lo;
                    int u = s*2 + a_uhalf;
                    int su = u ^ ((row >> 1) & 3);
                    ldsm_x4(abase + (uint32_t)pl*8192 + (uint32_t)row*64 + (uint32_t)su*16, Af[pl][t]);
                }
                #pragma unroll
                for (int b = 0; b < 2; b++) {
                    int r = s*16 + b_r_lo;
                    int u = wn*4 + b*2 + b_uhalf;
                    int su = u ^ (r & 7);
                    ldsm_x4_t(bbase + (uint32_t)pl*8192 + (uint32_t)r*256 + (uint32_t)su*16, Bf[pl][b]);
                }
            }
            #pragma unroll
            for (int t = 0; t < 2; t++) {
                #pragma unroll
                for (int b = 0; b < 2; b++) {
                    #pragma unroll
                    for (int h = 0; h < 2; h++) {
                        int j = b*2 + h;
                        uint32_t b0h = Bf[0][b][h*2], b1h = Bf[0][b][h*2+1];
                        uint32_t b0m = Bf[1][b][h*2], b1m = Bf[1][b][h*2+1];
                        // hh: fresh product, drained via fp32 FADD (sequential k order)
                        float dtmp[4];
                        mma_f16_zc(dtmp, Af[0][t], b0h, b1h);
                        chi[t][j][0] += dtmp[0];
                        chi[t][j][1] += dtmp[1];
                        chi[t][j][2] += dtmp[2];
                        chi[t][j][3] += dtmp[3];
                        // corrections (x 2^11): in-TC accumulate
                        mma_f16(clo[t][j], Af[0][t], b0m, b1m);  // Ah * wM'
                        mma_f16(clo[t][j], Af[1][t], b0h, b1h);  // Am' * wH
                    }
                }
            }
        }
        // loads AFTER compute (keeps LSU off the MMA critical path);
        // target stage (iter+3)&3 == (iter-1)&3, safe past this iter's barrier
        if (iter + 3 < 288) conv_issue_load(iter + 3, sbase, mbase, ntile, tid);
    }

    // epilogue: BN + ReLU, direct stores to g_Xt[pos][oc]
    __syncthreads();
    #pragma unroll
    for (int t = 0; t < 2; t++) {
        #pragma unroll
        for (int j = 0; j < 4; j++) {
            int oc_l = wn*32 + j*8 + (lane & 3)*2;
            float sc0 = s_sc[oc_l],   sh0 = s_sh[oc_l];
            float sc1 = s_sc[oc_l+1], sh1 = s_sh[oc_l+1];
            int r0 = mbase + wm*32 + t*16 + (lane >> 2);
            int r1 = r0 + 8;
            float a0 = chi[t][j][0] + clo[t][j][0]*RES_INV;
            float a1 = chi[t][j][1] + clo[t][j][1]*RES_INV;
            float a2 = chi[t][j][2] + clo[t][j][2]*RES_INV;
            float a3 = chi[t][j][3] + clo[t][j][3]*RES_INV;
            float2 v0, v1;
            v0.x = fmaxf(a0*sc0 + sh0, 0.f);
            v0.y = fmaxf(a1*sc1 + sh1, 0.f);
            v1.x = fmaxf(a2*sc0 + sh0, 0.f);
            v1.y = fmaxf(a3*sc1 + sh1, 0.f);
            *(float2*)&g_Xt[(size_t)r0*512 + ntile*128 + oc_l] = v0;
            *(float2*)&g_Xt[(size_t)r1*512 + ntile*128 + oc_l] = v1;
        }
    }
}

// ---------------- heads 1x1 GEMM ----------------
__global__ void __launch_bounds__(256) heads_kernel(
    const float* __restrict__ score_b, const float* __restrict__ bbox_b) {
    __shared__ float sv[32][33];
    __shared__ float sw[32][96];
    const int pos0 = blockIdx.x * 32;
    const int tid = threadIdx.x;
    const int og = tid & 31, pg = tid >> 5;

    float acc[3][4];
    #pragma unroll
    for (int m=0;m<3;m++)
        #pragma unroll
        for (int q=0;q<4;q++) acc[m][q]=0.f;

    for (int c0=0; c0<512; c0+=32) {
        {
            int pos_l = tid >> 5, c_l = tid & 31;
            #pragma unroll
            for (int r=0;r<4;r++)
                sv[c_l][pos_l + r*8] = g_Xt[(size_t)(pos0 + pos_l + r*8)*512 + c0 + c_l];
        }
        #pragma unroll
        for (int r=0;r<12;r++) {
            int e = r*256 + tid;
            int ccc = e/96, oo = e%96;
            sw[ccc][oo] = g_wpad[(size_t)(c0+ccc)*96 + oo];
        }
        __syncthreads();
        #pragma unroll
        for (int c=0;c<32;c++) {
            float w0 = sw[c][og], w1 = sw[c][og+32], w2 = sw[c][og+64];
            #pragma unroll
            for (int q=0;q<4;q++) {
                float v = sv[c][pg*4 + q];
                acc[0][q] += w0*v; acc[1][q] += w1*v; acc[2][q] += w2*v;
            }
        }
        __syncthreads();
    }
    #pragma unroll
    for (int m=0;m<3;m++) {
        int o = og + m*32;
        if (o >= 90) continue;
        float b = (o < 30) ? score_b[o] : bbox_b[o-30];
        #pragma unroll
        for (int q=0;q<4;q++)
            g_dots[(size_t)(pos0 + pg*4 + q)*96 + o] = acc[m][q] + b;
    }
}

// ---------------- per-anchor proposal prep ----------------
__global__ void proposal_kernel(const float* __restrict__ im_info) {
    int i = blockIdx.x*256 + threadIdx.x;
    if (i >= NANCH) return;
    int pos = i / NA, a = i % NA;
    int hy = pos / 96, wx = pos % 96;
    const float* dt = &g_dots[(size_t)pos*96];

    float bg = dt[a], fg = dt[15+a];
    float mx = fmaxf(bg, fg);
    float eb = expf(bg - mx), ef = expf(fg - mx);
    float score = ef / (eb + ef);

    float d0 = dt[30+4*a+0], d1 = dt[30+4*a+1], d2 = dt[30+4*a+2], d3 = dt[30+4*a+3];

    float ax1 = c_anchors[a][0] + wx*16.f;
    float ay1 = c_anchors[a][1] + hy*16.f;
    float ax2 = c_anchors[a][2] + wx*16.f;
    float ay2 = c_anchors[a][3] + hy*16.f;
    float aw = ax2 - ax1 + 1.f, ah = ay2 - ay1 + 1.f;
    float acx = ax1 + 0.5f*aw, acy = ay1 + 0.5f*ah;
    float px = d0*aw + acx, py = d1*ah + acy;
    float pw = expf(d2)*aw, ph = expf(d3)*ah;

    float imh = im_info[0], imw = im_info[1], ims = im_info[2];
    float x1 = fminf(fmaxf(px - 0.5f*pw, 0.f), imw - 1.f);
    float y1 = fminf(fmaxf(py - 0.5f*ph, 0.f), imh - 1.f);
    float x2 = fminf(fmaxf(px + 0.5f*pw - 1.f, 0.f), imw - 1.f);
    float y2 = fminf(fmaxf(py + 0.5f*ph - 1.f, 0.f), imh - 1.f);

    float ms = 16.f * ims;
    bool keep = ((x2 - x1 + 1.f) >= ms) && ((y2 - y1 + 1.f) >= ms);
    float s = keep ? score : -1.f;

    g_box[(size_t)i*4+0] = x1;
    g_box[(size_t)i*4+1] = y1;
    g_box[(size_t)i*4+2] = x2;
    g_box[(size_t)i*4+3] = y2;

    unsigned int b = __float_as_uint(s);
    unsigned int u = (b & 0x80000000u) ? ~b : (b | 0x80000000u);
    // low 32 bits = plain index; sort only bits [32,64) — stable LSD keeps
    // index-ascending order for score ties (reference top_k semantics)
    g_keys[i] = ((unsigned long long)u << 32) | (unsigned int)i;
}

__global__ void gather_kernel() {
    int j = blockIdx.x*256 + threadIdx.x;
    if (j >= PRE) return;
    unsigned long long k = g_keys_sorted[j];
    unsigned int idx = (unsigned int)(k & 0xFFFFFFFFull);
    int valid = (int)(k >> 63);
    float x1 = g_box[(size_t)idx*4+0], y1 = g_box[(size_t)idx*4+1];
    float x2 = g_box[(size_t)idx*4+2], y2 = g_box[(size_t)idx*4+3];
    g_bs[j*4+0]=x1; g_bs[j*4+1]=y1; g_bs[j*4+2]=x2; g_bs[j*4+3]=y2;
    g_area[j] = (x2 - x1 + 1.f) * (y2 - y1 + 1.f);
    g_valid[j] = valid;
}

__global__ void nms_mask_kernel() {
    // scan only ORs words >= word(i), so lower-triangle blocks are never read
    if (blockIdx.x < blockIdx.y) return;
    __shared__ float jb[64][4];
    __shared__ float ja[64];
    const int jw = blockIdx.x;
    const int t  = threadIdx.x;
    const int j0 = jw*64;
    if (j0 + t < PRE) {
        jb[t][0]=g_bs[(j0+t)*4+0]; jb[t][1]=g_bs[(j0+t)*4+1];
        jb[t][2]=g_bs[(j0+t)*4+2]; jb[t][3]=g_bs[(j0+t)*4+3];
        ja[t]=g_area[j0+t];
    }
    __syncthreads();
    const int i = blockIdx.y*64 + t;
    if (i >= PRE) return;
    float x1=g_bs[i*4+0], y1=g_bs[i*4+1], x2=g_bs[i*4+2], y2=g_bs[i*4+3];
    float ar=g_area[i];
    unsigned long long bits = 0ull;
    int lim = min(64, PRE - j0);
    for (int jj=0; jj<lim; jj++) {
        float xx1 = fmaxf(x1, jb[jj][0]);
        float yy1 = fmaxf(y1, jb[jj][1]);
        float xx2 = fminf(x2, jb[jj][2]);
        float yy2 = fminf(y2, jb[jj][3]);
        float iw = fmaxf(0.f, xx2 - xx1 + 1.f);
        float ih = fmaxf(0.f, yy2 - yy1 + 1.f);
        float inter = iw*ih;
        float iou = inter / (ar + ja[jj] - inter);
        if (iou > 0.7f) bits |= (1ull << jj);
    }
    g_mask[(size_t)i*NW + jw] = bits;
}

__global__ void nms_scan_kernel(float* __restrict__ rois) {
    __shared__ unsigned long long removed[NW];
    __shared__ int s_keep[POST];
    __shared__ int s_j;
    const int tid = threadIdx.x;
    for (int w = tid; w < NW; w += blockDim.x) {
        unsigned long long r = 0ull;
        for (int b = 0; b < 64; b++) {
            int j = w*64 + b;
            if (j >= PRE || !g_valid[j]) r |= (1ull << b);
        }
        removed[w] = r;
    }
    __syncthreads();

    int count = 0;
    for (int w = 0; w < NW; w++) {
        while (count < POST) {
            if (tid == 0) {
                unsigned long long live = ~removed[w];
                s_j = live ? (w*64 + __ffsll((long long)live) - 1) : -1;
            }
            __syncthreads();
            int j = s_j;
            __syncthreads();
            if (j < 0) break;
            if (tid == 0) s_keep[count] = j;
            count++;
            // scan only moves forward: words < w never revisited
            for (int ww = w + tid; ww < NW; ww += blockDim.x)
                removed[ww] |= g_mask[(size_t)j*NW + ww];
            __syncthreads();
        }
        if (count >= POST) break;
    }
    __syncthreads();

    for (int r = tid; r < POST; r += blockDim.x) {
        float b0=0.f,b1=0.f,b2=0.f,b3=0.f;
        if (r < count) {
            int j = s_keep[r];
            b0 = g_bs[j*4+0]; b1 = g_bs[j*4+1]; b2 = g_bs[j*4+2]; b3 = g_bs[j*4+3];
        }
        rois[r*5+0] = 0.f;
        rois[r*5+1] = b0; rois[r*5+2] = b1; rois[r*5+3] = b2; rois[r*5+4] = b3;
    }
}

// ---------------- launch ----------------
extern "C" void kernel_launch(void* const* d_in, const int* in_sizes, int n_in,
                              void* d_out, int out_size) {
    const float* features = (const float*)d_in[0];
    const float* im_info  = (const float*)d_in[1];
    const float* conv1_w  = (const float*)d_in[2];
    const float* conv1_b  = (const float*)d_in[3];
    const float* bn_gamma = (const float*)d_in[4];
    const float* bn_beta  = (const float*)d_in[5];
    const float* bn_mean  = (const float*)d_in[6];
    const float* bn_var   = (const float*)d_in[7];
    const float* score_w  = (const float*)d_in[8];
    const float* score_b  = (const float*)d_in[9];
    const float* bbox_w   = (const float*)d_in[10];
    const float* bbox_b   = (const float*)d_in[11];

    float* out = (float*)d_out;

    // 1) features passthrough
    cudaMemcpyAsync(out, features, (size_t)FEAT_ELEMS*sizeof(float),
                    cudaMemcpyDeviceToDevice, 0);

    // 2) prep: fp16 2-plane splits (scaled residual) + head weight pack
    split_feat_kernel<<<dim3(NPOS/32, CIN/32), dim3(32,32)>>>(features);
    split_w_kernel<<<(int)(((size_t)9*CIN*COUT + 255)/256), 256>>>(conv1_w);
    prep_wpad_kernel<<<(COUT*96 + 255)/256, 256>>>(score_w, bbox_w);

    // 3) conv1 + BN + ReLU via mma.sync fp16 2-plane, 4-stage single-barrier pipeline
    cudaFuncSetAttribute(conv_mma_kernel,
                         cudaFuncAttributeMaxDynamicSharedMemorySize, CONV_SMEM);
    conv_mma_kernel<<<dim3(72, 4), 512, CONV_SMEM>>>(
        conv1_b, bn_gamma, bn_beta, bn_mean, bn_var);

    // 4) heads
    heads_kernel<<<NPOS/32, 256>>>(score_b, bbox_b);

    // 5) per-anchor proposal prep
    proposal_kernel<<<(NANCH + 255)/256, 256>>>(im_info);

    // 6) sort keys descending on bits [32,64) only (stable -> index-asc ties)
    {
        void *keys_p = nullptr, *keys_sorted_p = nullptr, *temp_p = nullptr;
        cudaGetSymbolAddress(&keys_p, g_keys);
        cudaGetSymbolAddress(&keys_sorted_p, g_keys_sorted);
        cudaGetSymbolAddress(&temp_p, g_cub_temp);
        size_t tb = 0;
        cub::DeviceRadixSort::SortKeysDescending(
            nullptr, tb,
            (const unsigned long long*)keys_p, (unsigned long long*)keys_sorted_p,
            NANCH, 32, 64, (cudaStream_t)0);
        if (tb > sizeof(g_cub_temp)) tb = sizeof(g_cub_temp);
        cub::DeviceRadixSort::SortKeysDescending(
            temp_p, tb,
            (const unsigned long long*)keys_p, (unsigned long long*)keys_sorted_p,
            NANCH, 32, 64, (cudaStream_t)0);
    }

    // 7) gather top-6000
    gather_kernel<<<(PRE + 255)/256, 256>>>();

    // 8) NMS mask (upper triangle only)
    nms_mask_kernel<<<dim3(NW, NW), 64>>>();

    // 9) NMS scan + write rois
    nms_scan_kernel<<<1, 128>>>(out + FEAT_ELEMS);

    (void)in_sizes; (void)n_in; (void)out_size;
}

// round 13
// speedup vs baseline: 1.2941x; 1.2329x over previous
#include <cuda_runtime.h>
#include <cuda_fp16.h>
#include <cub/cub.cuh>
#include <stdint.h>

// ---------------- problem constants ----------------
#define HF 96
#define WF 96
#define NPOS (HF*WF)            // 9216
#define CIN 1024
#define COUT 512
#define NA 15
#define NANCH (NPOS*NA)         // 138240
#define PRE 6000
#define POST 300
#define NW 94                   // ceil(6000/64)
#define FEAT_ELEMS (1*1024*96*96)

#define RES_SCALE 2048.0f       // 2^11: residual planes scaled into fp16 normal range
#define RES_INV   (1.0f/2048.0f)

// ---------------- device scratch (static, no allocs) ----------------
__device__ __half g_featH[(size_t)NPOS*CIN];
__device__ __half g_featM[(size_t)NPOS*CIN];   // (A - Ah) * 2^11
__device__ __half g_wH[(size_t)9*CIN*COUT];    // [tap][ic][oc]
__device__ __half g_wM[(size_t)9*CIN*COUT];    // (w - wH) * 2^11
__device__ float g_Xt[(size_t)NPOS*COUT];      // conv1+BN+ReLU, [pos][oc]
__device__ float g_wpad[COUT*96];
__device__ float g_dots[(size_t)NPOS*96];
__device__ float g_box[(size_t)NANCH*4];
__device__ unsigned long long g_keys[NANCH];
__device__ unsigned long long g_keys_sorted[NANCH];
__device__ float g_bs[PRE*4];
__device__ float g_area[PRE];
__device__ int   g_valid[PRE];
__device__ unsigned long long g_mask[(size_t)PRE*NW];
__device__ unsigned char g_cub_temp[16u*1024u*1024u];

__constant__ float c_anchors[NA][4] = {
  {-15.f,  -4.f,  30.f,  19.f}, { -38.f, -16.f,  53.f,  31.f}, { -84.f, -40.f,  99.f,  55.f},
  {-176.f, -88.f, 191.f, 103.f}, {-360.f,-184.f, 375.f, 199.f},
  { -8.f,  -8.f,  23.f,  23.f}, { -24.f, -24.f,  39.f,  39.f}, { -56.f, -56.f,  71.f,  71.f},
  {-120.f,-120.f, 135.f, 135.f}, {-248.f,-248.f, 263.f, 263.f},
  { -3.f, -14.f,  18.f,  29.f}, { -14.f, -36.f,  29.f,  51.f}, { -36.f, -80.f,  51.f,  95.f},
  { -80.f,-168.f,  95.f, 183.f}, {-168.f,-344.f, 183.f, 359.f}
};

// ================= generic PTX helpers =================
__device__ __forceinline__ uint32_t smem_to_u32(const void* p) {
    uint32_t a;
    asm("{ .reg .u64 t; cvta.to.shared.u64 t, %1; cvt.u32.u64 %0, t; }" : "=r"(a) : "l"(p));
    return a;
}
__device__ __forceinline__ void cp16(uint32_t dst, const void* src, bool valid) {
    int sz = valid ? 16 : 0;
    asm volatile("cp.async.cg.shared.global [%0], [%1], 16, %2;"
                 :: "r"(dst), "l"(src), "r"(sz) : "memory");
}
#define CP_COMMIT()  asm volatile("cp.async.commit_group;" ::: "memory")
#define CP_WAIT2()   asm volatile("cp.async.wait_group 2;" ::: "memory")
#define CP_WAIT0()   asm volatile("cp.async.wait_group 0;" ::: "memory")

__device__ __forceinline__ void ldsm_x4(uint32_t addr, uint32_t* r) {
    asm volatile("ldmatrix.sync.aligned.m8n8.x4.shared.b16 {%0,%1,%2,%3}, [%4];"
                 : "=r"(r[0]), "=r"(r[1]), "=r"(r[2]), "=r"(r[3]) : "r"(addr));
}
__device__ __forceinline__ void ldsm_x4_t(uint32_t addr, uint32_t* r) {
    asm volatile("ldmatrix.sync.aligned.m8n8.x4.trans.shared.b16 {%0,%1,%2,%3}, [%4];"
                 : "=r"(r[0]), "=r"(r[1]), "=r"(r[2]), "=r"(r[3]) : "r"(addr));
}
// fp16 MMA, in-TC accumulate (used only for scaled correction terms)
__device__ __forceinline__ void mma_f16(float* d, const uint32_t* a, uint32_t b0, uint32_t b1) {
    asm volatile("mma.sync.aligned.m16n8k16.row.col.f32.f16.f16.f32 "
                 "{%0,%1,%2,%3},{%4,%5,%6,%7},{%8,%9},{%0,%1,%2,%3};"
                 : "+f"(d[0]), "+f"(d[1]), "+f"(d[2]), "+f"(d[3])
                 : "r"(a[0]), "r"(a[1]), "r"(a[2]), "r"(a[3]), "r"(b0), "r"(b1));
}
// zero-C fp16 MMA: D = A*B (large accumulator kept OUT of the TC truncating datapath)
__device__ __forceinline__ void mma_f16_zc(float* d, const uint32_t* a, uint32_t b0, uint32_t b1) {
    asm volatile("mma.sync.aligned.m16n8k16.row.col.f32.f16.f16.f32 "
                 "{%0,%1,%2,%3},{%4,%5,%6,%7},{%8,%9},{%10,%11,%12,%13};"
                 : "=f"(d[0]), "=f"(d[1]), "=f"(d[2]), "=f"(d[3])
                 : "r"(a[0]), "r"(a[1]), "r"(a[2]), "r"(a[3]), "r"(b0), "r"(b1),
                   "f"(0.f), "f"(0.f), "f"(0.f), "f"(0.f));
}

// ---------------- prep: split features fp32 -> 2 fp16 planes (scaled residual) ----------------
__global__ void split_feat_kernel(const float* __restrict__ in) {
    __shared__ float tile[32][33];
    int px = blockIdx.x*32 + threadIdx.x;
    int ic = blockIdx.y*32 + threadIdx.y;
    tile[threadIdx.y][threadIdx.x] = in[(size_t)ic*NPOS + px];
    __syncthreads();
    int opos = blockIdx.x*32 + threadIdx.y;
    int oic  = blockIdx.y*32 + threadIdx.x;
    float v = tile[threadIdx.x][threadIdx.y];
    __half h = __float2half(v);
    __half m = __float2half((v - __half2float(h)) * RES_SCALE);
    size_t o = (size_t)opos*CIN + oic;
    g_featH[o] = h; g_featM[o] = m;
}

// ---------------- prep: split conv weights -> [tap][ic][oc], scaled residual ----------------
__global__ void split_w_kernel(const float* __restrict__ w) {
    size_t t = (size_t)blockIdx.x*256 + threadIdx.x;
    if (t >= (size_t)9*CIN*COUT) return;
    int tap = (int)(t / (CIN*COUT));
    int rem = (int)(t % (CIN*COUT));
    int ic = rem / COUT, oc = rem % COUT;
    float v = w[((size_t)oc*CIN + ic)*9 + tap];
    __half h = __float2half(v);
    __half m = __float2half((v - __half2float(h)) * RES_SCALE);
    size_t o = ((size_t)tap*CIN + ic)*COUT + oc;
    g_wH[o] = h; g_wM[o] = m;
}

// ---------------- prep: pack head weights ----------------
__global__ void prep_wpad_kernel(const float* __restrict__ score_w,
                                 const float* __restrict__ bbox_w) {
    int t = blockIdx.x*256 + threadIdx.x;
    if (t >= COUT*96) return;
    int c = t / 96, o = t % 96;
    float v = 0.f;
    if (o < 30)       v = score_w[(size_t)o*512 + c];
    else if (o < 90)  v = bbox_w[(size_t)(o-30)*512 + c];
    g_wpad[t] = v;
}

// ================= conv1 via mma.sync fp16 2-plane (round-10 structure, unchanged) ====
// CTA tile: 128M x 128N, 512 threads = 4(m) x 4(n) warps, warp tile 32M x 32N.
// K: 9 taps x 32 ic-chunks = 288 iters, 3-stage pipeline, loads AFTER compute.
// hh: zero-C MMA per k16 step, drained to fp32 regs via FADD (sequential-k order).
// Corrections hm+mh (x 2^11) accumulate in-TC; epilogue adds clo * 2^-11.
#define STAGE   32768
#define B_OFF   16384
#define CONV_SMEM (3*STAGE + 1024)

__device__ __forceinline__ void conv_issue_load(int iter, uint32_t sbase, int mbase,
                                                int ntile, int tid) {
    const int tap = iter >> 5;
    const int chunk = iter & 31;
    const int ky = tap/3 - 1, kx = tap%3 - 1;
    const uint32_t stg = sbase + (uint32_t)(iter % 3)*STAGE;
    // ---- A: 128 rows x 4 uint4 x 2 planes ----
    {
        int row = tid >> 2, u = tid & 3;
        int p = mbase + row;
        int yy = p/96 + ky, xx = p%96 + kx;
        bool valid = ((unsigned)yy < 96u) && ((unsigned)xx < 96u);
        size_t idx = 0;
        if (valid) idx = ((size_t)(p + ky*96 + kx)*128 + chunk*4 + u) * 16;  // bytes
        uint32_t su = (uint32_t)(u ^ ((row >> 1) & 3));
        uint32_t dst = stg + (uint32_t)row*64 + su*16;
        cp16(dst,        (const char*)g_featH + idx, valid);
        cp16(dst + 8192, (const char*)g_featM + idx, valid);
    }
    // ---- B: 32 k-rows x 16 uint4 (128 oc) x 2 planes ----
    {
        int row = tid >> 4, u = tid & 15;
        uint32_t su = (uint32_t)(u ^ (row & 7));
        uint32_t dst = stg + B_OFF + (uint32_t)row*256 + su*16;
        size_t off = (((size_t)tap*CIN + chunk*32 + row)*COUT + (size_t)ntile*128 + u*8) * 2;
        cp16(dst,        (const char*)g_wH + off, true);
        cp16(dst + 8192, (const char*)g_wM + off, true);
    }
    CP_COMMIT();
}

__global__ void __launch_bounds__(512, 1) conv_mma_kernel(
    const float* __restrict__ conv_b, const float* __restrict__ gamma,
    const float* __restrict__ beta, const float* __restrict__ mean,
    const float* __restrict__ var) {
    extern __shared__ char smem_raw[];
    uint32_t sb0 = smem_to_u32(smem_raw);
    uint32_t sbase = (sb0 + 1023u) & ~1023u;

    __shared__ float s_sc[128];
    __shared__ float s_sh[128];

    const int tid = threadIdx.x;
    const int lane = tid & 31;
    const int wid = tid >> 5;
    const int wm = wid & 3;        // warp m (0..3) -> 32 rows each
    const int wn = wid >> 2;       // warp n (0..3) -> 32 oc each
    const int mbase = blockIdx.x * 128;
    const int ntile = blockIdx.y;  // 0..3, 128 oc each

    if (tid < 128) {
        int oc = ntile*128 + tid;
        float sc = gamma[oc] / sqrtf(var[oc] + 1e-5f);
        s_sc[tid] = sc;
        s_sh[tid] = (conv_b[oc] - mean[oc]) * sc + beta[oc];
    }

    float chi[2][4][4], clo[2][4][4];
    #pragma unroll
    for (int t = 0; t < 2; t++)
        #pragma unroll
        for (int j = 0; j < 4; j++)
            #pragma unroll
            for (int q = 0; q < 4; q++) { chi[t][j][q] = 0.f; clo[t][j][q] = 0.f; }

    conv_issue_load(0, sbase, mbase, ntile, tid);
    conv_issue_load(1, sbase, mbase, ntile, tid);
    conv_issue_load(2, sbase, mbase, ntile, tid);

    const int a_row_lo = ((lane >> 3) & 1)*8 + (lane & 7);
    const int a_uhalf = lane >> 4;
    const int b_r_lo = ((lane >> 3) & 1)*8 + (lane & 7);
    const int b_uhalf = lane >> 4;

    for (int iter = 0; iter < 288; iter++) {
        if (iter >= 285) { CP_WAIT0(); } else { CP_WAIT2(); }
        __syncthreads();

        const uint32_t abase = sbase + (uint32_t)(iter % 3)*STAGE;
        const uint32_t bbase = abase + B_OFF;

        #pragma unroll
        for (int s = 0; s < 2; s++) {
            uint32_t Af[2][2][4];
            uint32_t Bf[2][2][4];
            #pragma unroll
            for (int pl = 0; pl < 2; pl++) {
                #pragma unroll
                for (int t = 0; t < 2; t++) {
                    int row = wm*32 + t*16 + a_row_lo;
                    int u = s*2 + a_uhalf;
                    int su = u ^ ((row >> 1) & 3);
                    ldsm_x4(abase + (uint32_t)pl*8192 + (uint32_t)row*64 + (uint32_t)su*16, Af[pl][t]);
                }
                #pragma unroll
                for (int b = 0; b < 2; b++) {
                    int r = s*16 + b_r_lo;
                    int u = wn*4 + b*2 + b_uhalf;
                    int su = u ^ (r & 7);
                    ldsm_x4_t(bbase + (uint32_t)pl*8192 + (uint32_t)r*256 + (uint32_t)su*16, Bf[pl][b]);
                }
            }
            #pragma unroll
            for (int t = 0; t < 2; t++) {
                #pragma unroll
                for (int b = 0; b < 2; b++) {
                    #pragma unroll
                    for (int h = 0; h < 2; h++) {
                        int j = b*2 + h;
                        uint32_t b0h = Bf[0][b][h*2], b1h = Bf[0][b][h*2+1];
                        uint32_t b0m = Bf[1][b][h*2], b1m = Bf[1][b][h*2+1];
                        // hh: fresh product, drained via fp32 FADD (sequential k order)
                        float dtmp[4];
                        mma_f16_zc(dtmp, Af[0][t], b0h, b1h);
                        chi[t][j][0] += dtmp[0];
                        chi[t][j][1] += dtmp[1];
                        chi[t][j][2] += dtmp[2];
                        chi[t][j][3] += dtmp[3];
                        // corrections (x 2^11): in-TC accumulate
                        mma_f16(clo[t][j], Af[0][t], b0m, b1m);  // Ah * wM'
                        mma_f16(clo[t][j], Af[1][t], b0h, b1h);  // Am' * wH
                    }
                }
            }
        }
        __syncthreads();
        if (iter + 3 < 288) conv_issue_load(iter + 3, sbase, mbase, ntile, tid);
    }

    // epilogue: BN + ReLU, direct stores to g_Xt[pos][oc]
    __syncthreads();
    #pragma unroll
    for (int t = 0; t < 2; t++) {
        #pragma unroll
        for (int j = 0; j < 4; j++) {
            int oc_l = wn*32 + j*8 + (lane & 3)*2;
            float sc0 = s_sc[oc_l],   sh0 = s_sh[oc_l];
            float sc1 = s_sc[oc_l+1], sh1 = s_sh[oc_l+1];
            int r0 = mbase + wm*32 + t*16 + (lane >> 2);
            int r1 = r0 + 8;
            float a0 = chi[t][j][0] + clo[t][j][0]*RES_INV;
            float a1 = chi[t][j][1] + clo[t][j][1]*RES_INV;
            float a2 = chi[t][j][2] + clo[t][j][2]*RES_INV;
            float a3 = chi[t][j][3] + clo[t][j][3]*RES_INV;
            float2 v0, v1;
            v0.x = fmaxf(a0*sc0 + sh0, 0.f);
            v0.y = fmaxf(a1*sc1 + sh1, 0.f);
            v1.x = fmaxf(a2*sc0 + sh0, 0.f);
            v1.y = fmaxf(a3*sc1 + sh1, 0.f);
            *(float2*)&g_Xt[(size_t)r0*512 + ntile*128 + oc_l] = v0;
            *(float2*)&g_Xt[(size_t)r1*512 + ntile*128 + oc_l] = v1;
        }
    }
}

// ---------------- heads 1x1 GEMM ----------------
__global__ void __launch_bounds__(256) heads_kernel(
    const float* __restrict__ score_b, const float* __restrict__ bbox_b) {
    __shared__ float sv[32][33];
    __shared__ float sw[32][96];
    const int pos0 = blockIdx.x * 32;
    const int tid = threadIdx.x;
    const int og = tid & 31, pg = tid >> 5;

    float acc[3][4];
    #pragma unroll
    for (int m=0;m<3;m++)
        #pragma unroll
        for (int q=0;q<4;q++) acc[m][q]=0.f;

    for (int c0=0; c0<512; c0+=32) {
        {
            int pos_l = tid >> 5, c_l = tid & 31;
            #pragma unroll
            for (int r=0;r<4;r++)
                sv[c_l][pos_l + r*8] = g_Xt[(size_t)(pos0 + pos_l + r*8)*512 + c0 + c_l];
        }
        #pragma unroll
        for (int r=0;r<12;r++) {
            int e = r*256 + tid;
            int ccc = e/96, oo = e%96;
            sw[ccc][oo] = g_wpad[(size_t)(c0+ccc)*96 + oo];
        }
        __syncthreads();
        #pragma unroll
        for (int c=0;c<32;c++) {
            float w0 = sw[c][og], w1 = sw[c][og+32], w2 = sw[c][og+64];
            #pragma unroll
            for (int q=0;q<4;q++) {
                float v = sv[c][pg*4 + q];
                acc[0][q] += w0*v; acc[1][q] += w1*v; acc[2][q] += w2*v;
            }
        }
        __syncthreads();
    }
    #pragma unroll
    for (int m=0;m<3;m++) {
        int o = og + m*32;
        if (o >= 90) continue;
        float b = (o < 30) ? score_b[o] : bbox_b[o-30];
        #pragma unroll
        for (int q=0;q<4;q++)
            g_dots[(size_t)(pos0 + pg*4 + q)*96 + o] = acc[m][q] + b;
    }
}

// ---------------- per-anchor proposal prep ----------------
__global__ void proposal_kernel(const float* __restrict__ im_info) {
    int i = blockIdx.x*256 + threadIdx.x;
    if (i >= NANCH) return;
    int pos = i / NA, a = i % NA;
    int hy = pos / 96, wx = pos % 96;
    const float* dt = &g_dots[(size_t)pos*96];

    float bg = dt[a], fg = dt[15+a];
    float mx = fmaxf(bg, fg);
    float eb = expf(bg - mx), ef = expf(fg - mx);
    float score = ef / (eb + ef);

    float d0 = dt[30+4*a+0], d1 = dt[30+4*a+1], d2 = dt[30+4*a+2], d3 = dt[30+4*a+3];

    float ax1 = c_anchors[a][0] + wx*16.f;
    float ay1 = c_anchors[a][1] + hy*16.f;
    float ax2 = c_anchors[a][2] + wx*16.f;
    float ay2 = c_anchors[a][3] + hy*16.f;
    float aw = ax2 - ax1 + 1.f, ah = ay2 - ay1 + 1.f;
    float acx = ax1 + 0.5f*aw, acy = ay1 + 0.5f*ah;
    float px = d0*aw + acx, py = d1*ah + acy;
    float pw = expf(d2)*aw, ph = expf(d3)*ah;

    float imh = im_info[0], imw = im_info[1], ims = im_info[2];
    float x1 = fminf(fmaxf(px - 0.5f*pw, 0.f), imw - 1.f);
    float y1 = fminf(fmaxf(py - 0.5f*ph, 0.f), imh - 1.f);
    float x2 = fminf(fmaxf(px + 0.5f*pw - 1.f, 0.f), imw - 1.f);
    float y2 = fminf(fmaxf(py + 0.5f*ph - 1.f, 0.f), imh - 1.f);

    float ms = 16.f * ims;
    bool keep = ((x2 - x1 + 1.f) >= ms) && ((y2 - y1 + 1.f) >= ms);
    float s = keep ? score : -1.f;

    g_box[(size_t)i*4+0] = x1;
    g_box[(size_t)i*4+1] = y1;
    g_box[(size_t)i*4+2] = x2;
    g_box[(size_t)i*4+3] = y2;

    unsigned int b = __float_as_uint(s);
    unsigned int u = (b & 0x80000000u) ? ~b : (b | 0x80000000u);
    // low 32 bits = plain index; sort only bits [32,64) — stable LSD keeps
    // index-ascending order for score ties (reference top_k semantics)
    g_keys[i] = ((unsigned long long)u << 32) | (unsigned int)i;
}

__global__ void gather_kernel() {
    int j = blockIdx.x*256 + threadIdx.x;
    if (j >= PRE) return;
    unsigned long long k = g_keys_sorted[j];
    unsigned int idx = (unsigned int)(k & 0xFFFFFFFFull);
    int valid = (int)(k >> 63);
    float x1 = g_box[(size_t)idx*4+0], y1 = g_box[(size_t)idx*4+1];
    float x2 = g_box[(size_t)idx*4+2], y2 = g_box[(size_t)idx*4+3];
    g_bs[j*4+0]=x1; g_bs[j*4+1]=y1; g_bs[j*4+2]=x2; g_bs[j*4+3]=y2;
    g_area[j] = (x2 - x1 + 1.f) * (y2 - y1 + 1.f);
    g_valid[j] = valid;
}

__global__ void nms_mask_kernel() {
    // scan only reads words >= word(i), so lower-triangle blocks are never read
    if (blockIdx.x < blockIdx.y) return;
    __shared__ float jb[64][4];
    __shared__ float ja[64];
    const int jw = blockIdx.x;
    const int t  = threadIdx.x;
    const int j0 = jw*64;
    if (j0 + t < PRE) {
        jb[t][0]=g_bs[(j0+t)*4+0]; jb[t][1]=g_bs[(j0+t)*4+1];
        jb[t][2]=g_bs[(j0+t)*4+2]; jb[t][3]=g_bs[(j0+t)*4+3];
        ja[t]=g_area[j0+t];
    }
    __syncthreads();
    const int i = blockIdx.y*64 + t;
    if (i >= PRE) return;
    float x1=g_bs[i*4+0], y1=g_bs[i*4+1], x2=g_bs[i*4+2], y2=g_bs[i*4+3];
    float ar=g_area[i];
    unsigned long long bits = 0ull;
    int lim = min(64, PRE - j0);
    for (int jj=0; jj<lim; jj++) {
        float xx1 = fmaxf(x1, jb[jj][0]);
        float yy1 = fmaxf(y1, jb[jj][1]);
        float xx2 = fminf(x2, jb[jj][2]);
        float yy2 = fminf(y2, jb[jj][3]);
        float iw = fmaxf(0.f, xx2 - xx1 + 1.f);
        float ih = fmaxf(0.f, yy2 - yy1 + 1.f);
        float inter = iw*ih;
        float iou = inter / (ar + ja[jj] - inter);
        if (iou > 0.7f) bits |= (1ull << jj);
    }
    g_mask[(size_t)i*NW + jw] = bits;
}

// ---------------- NMS scan: lazy per-word catch-up + diagonal-block serial loop ----------------
// Selection order identical to the forward-OR scheme: suppression from earlier
// words arrives via catch-up at word entry; same-word suppression via the
// cached diagonal block. Critical path per selection = 1 smem load + ffs.
__global__ void nms_scan_kernel(float* __restrict__ rois) {
    __shared__ unsigned long long diag[64];
    __shared__ unsigned long long s_red[4];
    __shared__ int s_keep[POST];
    __shared__ int s_count;
    const int tid = threadIdx.x;   // 128 threads
    const int lane = tid & 31, warp = tid >> 5;

    if (tid == 0) s_count = 0;
    __syncthreads();

    for (int w = 0; w < NW; w++) {
        // catch-up: OR masks of all previous selections (word w column) + invalid bits
        unsigned long long r = 0ull;
        int cnt = s_count;
        for (int s = tid; s < cnt; s += 128)
            r |= g_mask[(size_t)s_keep[s]*NW + w];
        if (tid < 64) {
            int j = w*64 + tid;
            bool dead = (j >= PRE) || !g_valid[j];
            if (dead) r |= (1ull << tid);
            diag[tid] = (j < PRE) ? g_mask[(size_t)j*NW + w] : 0ull;
        }
        // warp-shuffle OR reduce
        #pragma unroll
        for (int o = 16; o > 0; o >>= 1) {
            r |= __shfl_down_sync(0xFFFFFFFFu, r, o);
        }
        if (lane == 0) s_red[warp] = r;
        __syncthreads();

        if (tid == 0) {
            unsigned long long rem = s_red[0] | s_red[1] | s_red[2] | s_red[3];
            int count = s_count;
            while (count < POST) {
                unsigned long long live = ~rem;
                if (!live) break;
                int b = __ffsll((long long)live) - 1;
                s_keep[count++] = w*64 + b;
                rem |= diag[b];          // includes bit b itself (IoU(j,j)=1 > 0.7)
                rem |= (1ull << b);
            }
            s_count = count;
        }
        __syncthreads();
        if (s_count >= POST) break;
    }
    __syncthreads();

    int count = s_count;
    for (int r = tid; r < POST; r += 128) {
        float b0=0.f,b1=0.f,b2=0.f,b3=0.f;
        if (r < count) {
            int j = s_keep[r];
            b0 = g_bs[j*4+0]; b1 = g_bs[j*4+1]; b2 = g_bs[j*4+2]; b3 = g_bs[j*4+3];
        }
        rois[r*5+0] = 0.f;
        rois[r*5+1] = b0; rois[r*5+2] = b1; rois[r*5+3] = b2; rois[r*5+4] = b3;
    }
}

// ---------------- launch ----------------
extern "C" void kernel_launch(void* const* d_in, const int* in_sizes, int n_in,
                              void* d_out, int out_size) {
    const float* features = (const float*)d_in[0];
    const float* im_info  = (const float*)d_in[1];
    const float* conv1_w  = (const float*)d_in[2];
    const float* conv1_b  = (const float*)d_in[3];
    const float* bn_gamma = (const float*)d_in[4];
    const float* bn_beta  = (const float*)d_in[5];
    const float* bn_mean  = (const float*)d_in[6];
    const float* bn_var   = (const float*)d_in[7];
    const float* score_w  = (const float*)d_in[8];
    const float* score_b  = (const float*)d_in[9];
    const float* bbox_w   = (const float*)d_in[10];
    const float* bbox_b   = (const float*)d_in[11];

    float* out = (float*)d_out;

    // 1) features passthrough
    cudaMemcpyAsync(out, features, (size_t)FEAT_ELEMS*sizeof(float),
                    cudaMemcpyDeviceToDevice, 0);

    // 2) prep: fp16 2-plane splits (scaled residual) + head weight pack
    split_feat_kernel<<<dim3(NPOS/32, CIN/32), dim3(32,32)>>>(features);
    split_w_kernel<<<(int)(((size_t)9*CIN*COUT + 255)/256), 256>>>(conv1_w);
    prep_wpad_kernel<<<(COUT*96 + 255)/256, 256>>>(score_w, bbox_w);

    // 3) conv1 + BN + ReLU via mma.sync fp16 2-plane (round-10 structure)
    cudaFuncSetAttribute(conv_mma_kernel,
                         cudaFuncAttributeMaxDynamicSharedMemorySize, CONV_SMEM);
    conv_mma_kernel<<<dim3(72, 4), 512, CONV_SMEM>>>(
        conv1_b, bn_gamma, bn_beta, bn_mean, bn_var);

    // 4) heads
    heads_kernel<<<NPOS/32, 256>>>(score_b, bbox_b);

    // 5) per-anchor proposal prep
    proposal_kernel<<<(NANCH + 255)/256, 256>>>(im_info);

    // 6) sort keys descending on bits [32,64) only (stable -> index-asc ties)
    {
        void *keys_p = nullptr, *keys_sorted_p = nullptr, *temp_p = nullptr;
        cudaGetSymbolAddress(&keys_p, g_keys);
        cudaGetSymbolAddress(&keys_sorted_p, g_keys_sorted);
        cudaGetSymbolAddress(&temp_p, g_cub_temp);
        size_t tb = 0;
        cub::DeviceRadixSort::SortKeysDescending(
            nullptr, tb,
            (const unsigned long long*)keys_p, (unsigned long long*)keys_sorted_p,
            NANCH, 32, 64, (cudaStream_t)0);
        if (tb > sizeof(g_cub_temp)) tb = sizeof(g_cub_temp);
        cub::DeviceRadixSort::SortKeysDescending(
            temp_p, tb,
            (const unsigned long long*)keys_p, (unsigned long long*)keys_sorted_p,
            NANCH, 32, 64, (cudaStream_t)0);
    }

    // 7) gather top-6000
    gather_kernel<<<(PRE + 255)/256, 256>>>();

    // 8) NMS mask (upper triangle only)
    nms_mask_kernel<<<dim3(NW, NW), 64>>>();

    // 9) NMS scan + write rois
    nms_scan_kernel<<<1, 128>>>(out + FEAT_ELEMS);

    (void)in_sizes; (void)n_in; (void)out_size;
}